// round 14
// baseline (speedup 1.0000x reference)
#include <cuda_runtime.h>

#define NB 4
#define LL 4096
#define KMAX 64
#define NCODES 256
#define FULLM 0xffffffffu

// (batch, code) occupancy bitmaps: 4 * 256 * 128 words = 512 KB.
// K1 overwrites EVERY word each run (no atomics, no reset needed) ->
// deterministic across graph replays by construction.
__device__ unsigned int g_bits[NB * NCODES * (LL / 32)];

__device__ __forceinline__ int pack8(float4 a, float4 c) {
    return (a.x > 0.f)        | ((a.y > 0.f) << 1) |
           ((a.z > 0.f) << 2) | ((a.w > 0.f) << 3) |
           ((c.x > 0.f) << 4) | ((c.y > 0.f) << 5) |
           ((c.z > 0.f) << 6) | ((c.w > 0.f) << 7);
}

// K1: one warp per (batch, 32-key block). Pack the 32 codes, then a 256-ballot
// sweep produces the full 256-word slice (word for code c = match mask of this
// j-block) and stores it. Writes every bitmap word -> stale state impossible.
__global__ void __launch_bounds__(256)
k_bits(const float* __restrict__ key_up) {
    int gw   = blockIdx.x * 8 + (threadIdx.x >> 5);   // 0..511
    int lane = threadIdx.x & 31;
    int b    = gw >> 7;                               // batch
    int w    = gw & 127;                              // j-block
    int j    = w * 32 + lane;

    const float4* kb = reinterpret_cast<const float4*>(key_up + (size_t)b * LL * 8);
    int code = pack8(kb[j * 2], kb[j * 2 + 1]);

    unsigned int* dst = g_bits + ((b << 8) * (LL / 32)) + w;   // + c*128
    #pragma unroll
    for (int r = 0; r < 8; r++) {
        unsigned myw = 0;
        #pragma unroll
        for (int i = 0; i < 32; i++) {
            unsigned m = __ballot_sync(FULLM, code == r * 32 + i);
            if (i == lane) myw = m;
        }
        dst[(r * 32 + lane) * (LL / 32)] = myw;       // fire-and-forget
    }
}

// K2: one warp per query, output written directly. Pack the query code, load
// the (batch,code) bitmap (uint4/lane, 512B coalesced), popc+shfl-scan for
// ranks, extract set bits in ascending j into the padded row:
//   pad = max(0, 64-n) leading -1s, then min(n,64) smallest j ascending
// (== jnp.sort of the -1-padded first-64 match list). n>64 handled natively.
__global__ void __launch_bounds__(256)
k_find(const float* __restrict__ query_up, float* __restrict__ out) {
    int gw   = blockIdx.x * 8 + (threadIdx.x >> 5);   // query id 0..16383
    int lane = threadIdx.x & 31;
    int b    = gw >> 12;

    int part = 0;
    if (lane < 2) {
        float4 p = reinterpret_cast<const float4*>(query_up)[gw * 2 + lane];
        int nib = (p.x > 0.f)        | ((p.y > 0.f) << 1) |
                  ((p.z > 0.f) << 2) | ((p.w > 0.f) << 3);
        part = nib << (4 * lane);
    }
    part |= __shfl_xor_sync(FULLM, part, 1);
    int code = __shfl_sync(FULLM, part, 0);

    uint4 wv = reinterpret_cast<const uint4*>(
                   g_bits + (((b << 8) | code) * (LL / 32)))[lane];

    int c = __popc(wv.x) + __popc(wv.y) + __popc(wv.z) + __popc(wv.w);
    int inc = c;
    #pragma unroll
    for (int d = 1; d < 32; d <<= 1) {
        int u = __shfl_up_sync(FULLM, inc, d);
        if (lane >= d) inc += u;
    }
    int n    = __shfl_sync(FULLM, inc, 31);
    int rank = inc - c;
    int pad  = n < KMAX ? KMAX - n : 0;

    float* row = out + (size_t)gw * KMAX;
    if (lane      < pad) row[lane]      = -1.0f;
    if (lane + 32 < pad) row[lane + 32] = -1.0f;

    unsigned int ws[4] = {wv.x, wv.y, wv.z, wv.w};
    #pragma unroll
    for (int i = 0; i < 4; i++) {
        unsigned int w = ws[i];
        int jb = (lane * 4 + i) * 32;
        while (w) {
            int bit = __ffs(w) - 1;
            int pos = pad + rank;
            if (pos < KMAX) row[pos] = (float)(jb + bit);
            rank++;
            w &= w - 1;
        }
    }
}

extern "C" void kernel_launch(void* const* d_in, const int* in_sizes, int n_in,
                              void* d_out, int out_size) {
    // Identify inputs by element count (robust to metadata ordering).
    const float* query_up = nullptr;
    const float* key_up   = nullptr;
    for (int i = 0; i < n_in; i++) {
        if (in_sizes[i] == NB * LL * 8) {
            if (!query_up)      query_up = (const float*)d_in[i];
            else if (!key_up)   key_up   = (const float*)d_in[i];
        }
    }
    if (!query_up || !key_up) {
        query_up = (const float*)d_in[0];
        key_up   = (const float*)d_in[1];
    }
    float* out = (float*)d_out;

    k_bits<<<64, 256>>>(key_up);            // 512 warps, full bitmap rewrite
    k_find<<<2048, 256>>>(query_up, out);   // 16384 warps, 1 query each
}